// round 15
// baseline (speedup 1.0000x reference)
#include <cuda_runtime.h>
#include <cstdint>

#define GS     16
#define NPAIR  136          // 16*17/2 lower-triangular pairs
#define NACC   152          // 136 pair sums + 16 channel sums
#define GROUPS 32
#define BATCH  32
#define HW     3136         // 56*56
#define HW4    784          // HW/4 (float4 units)
#define CH     512

typedef unsigned long long ull;

static __device__ float d_acc[GROUPS][NACC];   // pair sums + channel sums
static __device__ float d_Linv[GROUPS][NPAIR]; // packed lower-triangular Linv
static __device__ float d_bias[CH];            // Linv @ mean, per channel

// ---- packed f32x2 helpers (Blackwell) --------------------------------------
__device__ __forceinline__ void fma2(ull& d, ull a, ull b) {
    asm("fma.rn.f32x2 %0, %1, %2, %0;" : "+l"(d) : "l"(a), "l"(b));
}
__device__ __forceinline__ void add2(ull& d, ull a) {
    asm("add.rn.f32x2 %0, %0, %1;" : "+l"(d) : "l"(a));
}
__device__ __forceinline__ float unpack_add(ull v) {
    float lo, hi;
    asm("mov.b64 {%0,%1}, %2;" : "=f"(lo), "=f"(hi) : "l"(v));
    return lo + hi;
}
__device__ __forceinline__ ull pack2(float lo, float hi) {
    ull r;
    asm("mov.b64 %0, {%1,%2};" : "=l"(r) : "f"(lo), "f"(hi));
    return r;
}

struct V2 { ull a, b; };   // one float4 = two packed f32x2 halves

__device__ __forceinline__ V2 ld_v2(const float4* p) {
    const float4 f = __ldg(p);
    V2 v;
    v.a = pack2(f.x, f.y);
    v.b = pack2(f.z, f.w);
    return v;
}

// ---- compile-time pair partition: pair (i,j) -> warp (i+j) & 7 -------------
// pcnt(W): 18,16,18,16,18,16,18,16 (sum 136). pidx gives static acc index.
__host__ __device__ constexpr int pidx(int I, int J, int W) {
    int n = 0;
    for (int i = 0; i < 16; i++)
        for (int j = 0; j <= i; j++)
            if (((i + j) & 7) == W) {
                if (i == I && j == J) return n;
                n++;
            }
    return -1;
}

template <int W, int I, int J>
__device__ __forceinline__ void accum_rec(const V2 (&v)[16], ull* acc) {
    if constexpr (((I + J) & 7) == W) {
        constexpr int k = pidx(I, J, W);
        fma2(acc[k], v[I].a, v[J].a);
        fma2(acc[k], v[I].b, v[J].b);
    }
    if constexpr (J < I)       accum_rec<W, I, J + 1>(v, acc);
    else if constexpr (I < 15) accum_rec<W, I + 1, 0>(v, acc);
}

template <int W, int I, int J>
__device__ __forceinline__ void emit_rec(ull* acc, float* d_accg, int lane) {
    if constexpr (((I + J) & 7) == W) {
        constexpr int k = pidx(I, J, W);
        float s = unpack_add(acc[k]);
#pragma unroll
        for (int off = 16; off > 0; off >>= 1)
            s += __shfl_xor_sync(0xffffffffu, s, off);
        if (lane == 0) atomicAdd(&d_accg[I * (I + 1) / 2 + J], s);
    }
    if constexpr (J < I)       emit_rec<W, I, J + 1>(acc, d_accg, lane);
    else if constexpr (I < 15) emit_rec<W, I + 1, 0>(acc, d_accg, lane);
}

template <int W>
__device__ __forceinline__ void chunk_work(const float4* in, int cb, int lane,
                                           ull* acc, ull& sA, ull& sB) {
#pragma unroll
    for (int s = 0; s < 2; s++) {
        const int pos = cb + s * 32 + lane;
        V2 v[16];
#pragma unroll
        for (int c = 0; c < 16; c++) {
            if (pos < HW4) v[c] = ld_v2(in + (size_t)c * HW4 + pos);
            else           { v[c].a = 0ull; v[c].b = 0ull; }
        }
        accum_rec<W, 0, 0>(v, acc);
        add2(sA, v[2 * W].a);     add2(sA, v[2 * W].b);
        add2(sB, v[2 * W + 1].a); add2(sB, v[2 * W + 1].b);
    }
}

// ---------------------------------------------------------------------------
__global__ void zero_kernel() {
    int i = blockIdx.x * blockDim.x + threadIdx.x;
    if (i < GROUPS * NACC) ((float*)d_acc)[i] = 0.f;
}

// ---------------------------------------------------------------------------
// Stats v13: ONE block per tile (amp 1.0 = 205 MB DRAM), pairs split across
// the 8 WARPS by class (i+j)&7 -> <=18 packed accs/warp, static indices via
// templates (no dynamic reg indexing -> no spill). All warps re-read the tile
// from L1 (8x L1 amp; chunk working set 16 KB, barrier-paced -> L1-resident).
// ~114 regs -> 2 blocks/SM (16 warps). Floors: DRAM 30us, L1 ~45us.
__global__ void __launch_bounds__(256, 2) stats_kernel(const float* __restrict__ x) {
    const int g = blockIdx.x & 31;
    const int b = blockIdx.x >> 5;
    const float4* in = (const float4*)(x + ((size_t)b * CH + (size_t)g * GS) * HW);

    const int tid  = threadIdx.x;
    const int wid  = tid >> 5;
    const int lane = tid & 31;

    ull acc[18];
#pragma unroll
    for (int k = 0; k < 18; k++) acc[k] = 0ull;
    ull sA = 0ull, sB = 0ull;

    for (int cb = 0; cb < HW4; cb += 64) {
        switch (wid) {
            case 0: chunk_work<0>(in, cb, lane, acc, sA, sB); break;
            case 1: chunk_work<1>(in, cb, lane, acc, sA, sB); break;
            case 2: chunk_work<2>(in, cb, lane, acc, sA, sB); break;
            case 3: chunk_work<3>(in, cb, lane, acc, sA, sB); break;
            case 4: chunk_work<4>(in, cb, lane, acc, sA, sB); break;
            case 5: chunk_work<5>(in, cb, lane, acc, sA, sB); break;
            case 6: chunk_work<6>(in, cb, lane, acc, sA, sB); break;
            default: chunk_work<7>(in, cb, lane, acc, sA, sB); break;
        }
        __syncthreads();   // pace warps so the chunk stays L1-resident
    }

    switch (wid) {
        case 0: emit_rec<0, 0, 0>(acc, d_acc[g], lane); break;
        case 1: emit_rec<1, 0, 0>(acc, d_acc[g], lane); break;
        case 2: emit_rec<2, 0, 0>(acc, d_acc[g], lane); break;
        case 3: emit_rec<3, 0, 0>(acc, d_acc[g], lane); break;
        case 4: emit_rec<4, 0, 0>(acc, d_acc[g], lane); break;
        case 5: emit_rec<5, 0, 0>(acc, d_acc[g], lane); break;
        case 6: emit_rec<6, 0, 0>(acc, d_acc[g], lane); break;
        default: emit_rec<7, 0, 0>(acc, d_acc[g], lane); break;
    }

    // channel sums: warp W owns channels 2W, 2W+1
    float s1 = unpack_add(sA);
    float s2 = unpack_add(sB);
#pragma unroll
    for (int off = 16; off > 0; off >>= 1) {
        s1 += __shfl_xor_sync(0xffffffffu, s1, off);
        s2 += __shfl_xor_sync(0xffffffffu, s2, off);
    }
    if (lane == 0) {
        atomicAdd(&d_acc[g][NPAIR + 2 * wid],     s1);
        atomicAdd(&d_acc[g][NPAIR + 2 * wid + 1], s2);
    }
}

// ---------------------------------------------------------------------------
// Solve: one block per group, 16 threads, everything in shared memory, fp64.
__global__ void __launch_bounds__(16) solve_kernel() {
    const int g = blockIdx.x;
    const int t = threadIdx.x;
    __shared__ double P[GS][GS + 1];
    __shared__ double L[GS][GS + 1];
    __shared__ double V[GS][GS + 1];
    __shared__ double m[GS];

    const double Nd   = (double)BATCH * (double)HW;
    const double EPSd = 1e-3;
    const unsigned MASK = 0xffffu;

    m[t] = (double)d_acc[g][NPAIR + t] / Nd;
    __syncwarp(MASK);

    for (int j = 0; j < GS; j++) {
        const int i_ = t > j ? t : j, j_ = t > j ? j : t;
        double c = (double)d_acc[g][i_ * (i_ + 1) / 2 + j_] / Nd - m[t] * m[j];
        c *= (1.0 - EPSd);
        if (t == j) c += EPSd;
        P[t][j] = c;
    }
    __syncwarp(MASK);

    for (int j = 0; j < GS; j++) {
        if (t == j) {
            double s = P[j][j];
            for (int k = 0; k < j; k++) s -= L[j][k] * L[j][k];
            L[j][j] = sqrt(s);
        }
        __syncwarp(MASK);
        if (t > j) {
            double s = P[t][j];
            for (int k = 0; k < j; k++) s -= L[t][k] * L[j][k];
            L[t][j] = s / L[j][j];
        }
        __syncwarp(MASK);
    }

    V[t][t] = 1.0 / L[t][t];
    for (int i = t + 1; i < GS; i++) {
        double s = 0.0;
        for (int k = t; k < i; k++) s += L[i][k] * V[k][t];
        V[i][t] = -s / L[i][i];
    }
    __syncwarp(MASK);

    double bsum = 0.0;
    for (int j = 0; j <= t; j++) {
        d_Linv[g][t * (t + 1) / 2 + j] = (float)V[t][j];
        bsum += V[t][j] * m[j];
    }
    d_bias[g * GS + t] = (float)bsum;
}

// ---------------------------------------------------------------------------
// Apply (unchanged, proven ~66us / 68% DRAM):
// out_i = sum_{j<=i} Linv_ij * x_j - bias_i, float4, streaming stores.
__global__ void __launch_bounds__(256, 2) apply_kernel(const float* __restrict__ x,
                                                       float* __restrict__ out) {
    const int g = blockIdx.x & 31;
    const int b = blockIdx.x >> 5;

    __shared__ float Ls[NPAIR];
    __shared__ float bs[GS];
    if (threadIdx.x < NPAIR) Ls[threadIdx.x] = d_Linv[g][threadIdx.x];
    if (threadIdx.x < GS)    bs[threadIdx.x] = d_bias[g * GS + threadIdx.x];
    __syncthreads();

    const size_t off = ((size_t)b * CH + (size_t)g * GS) * HW;
    const float4* in = (const float4*)(x + off);
    float4*       op = (float4*)(out + off);

    for (int pos = threadIdx.x; pos < HW4; pos += 256) {
        float4 v[GS];
#pragma unroll
        for (int c = 0; c < GS; c++) v[c] = in[(size_t)c * HW4 + pos];
#pragma unroll
        for (int i = 0; i < GS; i++) {
            const float bias = bs[i];
            float4 a;
            a.x = -bias; a.y = -bias; a.z = -bias; a.w = -bias;
#pragma unroll
            for (int j = 0; j <= i; j++) {
                const float f = Ls[i * (i + 1) / 2 + j];
                a.x = fmaf(f, v[j].x, a.x);
                a.y = fmaf(f, v[j].y, a.y);
                a.z = fmaf(f, v[j].z, a.z);
                a.w = fmaf(f, v[j].w, a.w);
            }
            __stcs(&op[(size_t)i * HW4 + pos], a);
        }
    }
}

// ---------------------------------------------------------------------------
extern "C" void kernel_launch(void* const* d_in, const int* in_sizes, int n_in,
                              void* d_out, int out_size) {
    const float* x   = (const float*)d_in[0];
    float*       out = (float*)d_out;

    zero_kernel<<<(GROUPS * NACC + 255) / 256, 256>>>();
    stats_kernel<<<GROUPS * BATCH, 256>>>(x);
    solve_kernel<<<GROUPS, 16>>>();
    apply_kernel<<<GROUPS * BATCH, 256>>>(x, out);
}

// round 16
// speedup vs baseline: 1.5059x; 1.5059x over previous
#include <cuda_runtime.h>
#include <cstdint>

#define GS     16
#define NPAIR  136          // 16*17/2 lower-triangular pairs
#define NACC   152          // 136 pair sums + 16 channel sums
#define GROUPS 32
#define BATCH  32
#define HW     3136         // 56*56
#define HW4    784          // HW/4 (float4 units)
#define CH     512

typedef unsigned long long ull;

static __device__ float d_acc[GROUPS][NACC];   // pair sums + channel sums
static __device__ float d_Linv[GROUPS][NPAIR]; // packed lower-triangular Linv
static __device__ float d_bias[CH];            // Linv @ mean, per channel

// ---- packed f32x2 helpers (Blackwell) --------------------------------------
__device__ __forceinline__ void fma2(ull& d, ull a, ull b) {
    asm("fma.rn.f32x2 %0, %1, %2, %0;" : "+l"(d) : "l"(a), "l"(b));
}
__device__ __forceinline__ void add2(ull& d, ull a) {
    asm("add.rn.f32x2 %0, %0, %1;" : "+l"(d) : "l"(a));
}
__device__ __forceinline__ float unpack_add(ull v) {
    float lo, hi;
    asm("mov.b64 {%0,%1}, %2;" : "=f"(lo), "=f"(hi) : "l"(v));
    return lo + hi;
}

struct V2 { ull a, b; };   // one float4 = two packed f32x2 halves

// Direct LDG.E.128 into two u64 regs: NO pack MOVs (the R5 version spent
// 4 mov.b64 per load = ~39% of cross-role issue slots).
__device__ __forceinline__ V2 ld_v2(const float4* p) {
    V2 v;
    asm("ld.global.nc.v2.u64 {%0,%1}, [%2];" : "=l"(v.a), "=l"(v.b) : "l"(p));
    return v;
}

// ---------------------------------------------------------------------------
__global__ void zero_kernel() {
    int i = blockIdx.x * blockDim.x + threadIdx.x;
    if (i < GROUPS * NACC) ((float*)d_acc)[i] = 0.f;
}

// ---------------------------------------------------------------------------
// Stats v3b: EXACT revert to the best-measured stats (R5, 106us) with the one
// defect removed (pack MOVs -> direct v2.u64 loads).
// 12 warps, 4 roles of 3 warps (96 lanes each), one block per (batch,group):
//   role 0: diag pairs in ch0-7   (36 packed acc + 8 packed sums)
//   role 1: diag pairs in ch8-15
//   role 2: cross i in 8-15, j in 0-3  (32 packed acc)
//   role 3: cross i in 8-15, j in 4-7
__global__ void __launch_bounds__(384) stats_kernel(const float* __restrict__ x) {
    const int g = blockIdx.x & 31;
    const int b = blockIdx.x >> 5;
    const float4* in = (const float4*)(x + ((size_t)b * CH + (size_t)g * GS) * HW);

    const int tid  = threadIdx.x;
    const int wid  = tid >> 5;
    const int lane = tid & 31;
    const int role = wid / 3;              // 0..3
    const int id   = tid - role * 96;      // 0..95 within role

    if (role < 2) {
        // ---------------- diagonal roles ------------------------------------
        const int co = role * 8;
        ull acc[36], sum[8];
#pragma unroll
        for (int k = 0; k < 36; k++) acc[k] = 0ull;
#pragma unroll
        for (int k = 0; k < 8; k++) sum[k] = 0ull;

        for (int pos = id; pos < HW4; pos += 96) {
            V2 v[8];
#pragma unroll
            for (int c = 0; c < 8; c++) v[c] = ld_v2(in + (size_t)(co + c) * HW4 + pos);
#pragma unroll
            for (int i = 0; i < 8; i++) {
#pragma unroll
                for (int j = 0; j <= i; j++) {
                    const int k = i * (i + 1) / 2 + j;
                    fma2(acc[k], v[i].a, v[j].a);
                    fma2(acc[k], v[i].b, v[j].b);
                }
                add2(sum[i], v[i].a);
                add2(sum[i], v[i].b);
            }
        }

        float r[44];
#pragma unroll
        for (int k = 0; k < 36; k++) r[k] = unpack_add(acc[k]);
#pragma unroll
        for (int k = 0; k < 8; k++)  r[36 + k] = unpack_add(sum[k]);
#pragma unroll
        for (int k = 0; k < 44; k++) {
#pragma unroll
            for (int off = 16; off > 0; off >>= 1)
                r[k] += __shfl_xor_sync(0xffffffffu, r[k], off);
        }
        if (lane == 0) {
            int k = 0;
            for (int i = 0; i < 8; i++)
                for (int j = 0; j <= i; j++) {
                    const int gi = i + co, gj = j + co;
                    atomicAdd(&d_acc[g][gi * (gi + 1) / 2 + gj], r[k++]);
                }
            for (int i = 0; i < 8; i++)
                atomicAdd(&d_acc[g][NPAIR + co + i], r[36 + i]);
        }
    } else {
        // ---------------- cross roles: i in 8-15, j in jo..jo+3 -------------
        const int jo = (role - 2) * 4;
        ull acc[32];
#pragma unroll
        for (int k = 0; k < 32; k++) acc[k] = 0ull;

        for (int pos = id; pos < HW4; pos += 96) {
            V2 u[8], w[4];
#pragma unroll
            for (int c = 0; c < 8; c++) u[c] = ld_v2(in + (size_t)(8 + c) * HW4 + pos);
#pragma unroll
            for (int c = 0; c < 4; c++) w[c] = ld_v2(in + (size_t)(jo + c) * HW4 + pos);
#pragma unroll
            for (int i = 0; i < 8; i++)
#pragma unroll
                for (int j = 0; j < 4; j++) {
                    const int k = i * 4 + j;
                    fma2(acc[k], u[i].a, w[j].a);
                    fma2(acc[k], u[i].b, w[j].b);
                }
        }

        float r[32];
#pragma unroll
        for (int k = 0; k < 32; k++) r[k] = unpack_add(acc[k]);
#pragma unroll
        for (int k = 0; k < 32; k++) {
#pragma unroll
            for (int off = 16; off > 0; off >>= 1)
                r[k] += __shfl_xor_sync(0xffffffffu, r[k], off);
        }
        if (lane == 0) {
            for (int i = 0; i < 8; i++)
                for (int j = 0; j < 4; j++) {
                    const int gi = 8 + i, gj = jo + j;
                    atomicAdd(&d_acc[g][gi * (gi + 1) / 2 + gj], r[i * 4 + j]);
                }
        }
    }
}

// ---------------------------------------------------------------------------
// Solve: one block per group, 16 threads, everything in shared memory, fp64.
__global__ void __launch_bounds__(16) solve_kernel() {
    const int g = blockIdx.x;
    const int t = threadIdx.x;
    __shared__ double P[GS][GS + 1];
    __shared__ double L[GS][GS + 1];
    __shared__ double V[GS][GS + 1];
    __shared__ double m[GS];

    const double Nd   = (double)BATCH * (double)HW;
    const double EPSd = 1e-3;
    const unsigned MASK = 0xffffu;

    m[t] = (double)d_acc[g][NPAIR + t] / Nd;
    __syncwarp(MASK);

    for (int j = 0; j < GS; j++) {
        const int i_ = t > j ? t : j, j_ = t > j ? j : t;
        double c = (double)d_acc[g][i_ * (i_ + 1) / 2 + j_] / Nd - m[t] * m[j];
        c *= (1.0 - EPSd);
        if (t == j) c += EPSd;
        P[t][j] = c;
    }
    __syncwarp(MASK);

    for (int j = 0; j < GS; j++) {
        if (t == j) {
            double s = P[j][j];
            for (int k = 0; k < j; k++) s -= L[j][k] * L[j][k];
            L[j][j] = sqrt(s);
        }
        __syncwarp(MASK);
        if (t > j) {
            double s = P[t][j];
            for (int k = 0; k < j; k++) s -= L[t][k] * L[j][k];
            L[t][j] = s / L[j][j];
        }
        __syncwarp(MASK);
    }

    V[t][t] = 1.0 / L[t][t];
    for (int i = t + 1; i < GS; i++) {
        double s = 0.0;
        for (int k = t; k < i; k++) s += L[i][k] * V[k][t];
        V[i][t] = -s / L[i][i];
    }
    __syncwarp(MASK);

    double bsum = 0.0;
    for (int j = 0; j <= t; j++) {
        d_Linv[g][t * (t + 1) / 2 + j] = (float)V[t][j];
        bsum += V[t][j] * m[j];
    }
    d_bias[g * GS + t] = (float)bsum;
}

// ---------------------------------------------------------------------------
// Apply (unchanged, proven ~65us / 69% DRAM):
// out_i = sum_{j<=i} Linv_ij * x_j - bias_i, float4, streaming stores.
__global__ void __launch_bounds__(256, 2) apply_kernel(const float* __restrict__ x,
                                                       float* __restrict__ out) {
    const int g = blockIdx.x & 31;
    const int b = blockIdx.x >> 5;

    __shared__ float Ls[NPAIR];
    __shared__ float bs[GS];
    if (threadIdx.x < NPAIR) Ls[threadIdx.x] = d_Linv[g][threadIdx.x];
    if (threadIdx.x < GS)    bs[threadIdx.x] = d_bias[g * GS + threadIdx.x];
    __syncthreads();

    const size_t off = ((size_t)b * CH + (size_t)g * GS) * HW;
    const float4* in = (const float4*)(x + off);
    float4*       op = (float4*)(out + off);

    for (int pos = threadIdx.x; pos < HW4; pos += 256) {
        float4 v[GS];
#pragma unroll
        for (int c = 0; c < GS; c++) v[c] = in[(size_t)c * HW4 + pos];
#pragma unroll
        for (int i = 0; i < GS; i++) {
            const float bias = bs[i];
            float4 a;
            a.x = -bias; a.y = -bias; a.z = -bias; a.w = -bias;
#pragma unroll
            for (int j = 0; j <= i; j++) {
                const float f = Ls[i * (i + 1) / 2 + j];
                a.x = fmaf(f, v[j].x, a.x);
                a.y = fmaf(f, v[j].y, a.y);
                a.z = fmaf(f, v[j].z, a.z);
                a.w = fmaf(f, v[j].w, a.w);
            }
            __stcs(&op[(size_t)i * HW4 + pos], a);
        }
    }
}

// ---------------------------------------------------------------------------
extern "C" void kernel_launch(void* const* d_in, const int* in_sizes, int n_in,
                              void* d_out, int out_size) {
    const float* x   = (const float*)d_in[0];
    float*       out = (float*)d_out;

    zero_kernel<<<(GROUPS * NACC + 255) / 256, 256>>>();
    stats_kernel<<<GROUPS * BATCH, 384>>>(x);
    solve_kernel<<<GROUPS, 16>>>();
    apply_kernel<<<GROUPS * BATCH, 256>>>(x, out);
}